// round 15
// baseline (speedup 1.0000x reference)
#include <cuda_runtime.h>
#include <math.h>

#define BATCH    16
#define NBOX     120000
#define NCH      22
#define NMS_MAX  400
#define NUM_PRED 10
#define BINS     1024
#define HBLK     64
#define CAP0     4096
#define THR0     0.984375f
#define SORTW    1024
#define MASKW    7
#define NTILE    (NBOX / 2)

// ---------------- scratch ----------------------------------------------------
__device__ int                g_cc[BATCH];     // zero-init; extract last block resets
__device__ int                g_done[BATCH];
__device__ int                g_m[BATCH];
__device__ int                g_fast[BATCH];
__device__ unsigned long long g_cand0[BATCH][CAP0];
__device__ float              g_sc[BATCH][NMS_MAX];
__device__ int                g_sidx[BATCH][NMS_MAX];
__device__ __align__(16) float g_bx[BATCH][NMS_MAX * 4];

__device__ __forceinline__ unsigned int fkey(float f) {
    unsigned int u = __float_as_uint(f);
    return (u & 0x80000000u) ? ~u : (u | 0x80000000u);
}
__device__ __forceinline__ float fkey_inv(unsigned int k) {
    unsigned int u = (k & 0x80000000u) ? (k & 0x7fffffffu) : ~k;
    return __uint_as_float(u);
}
__device__ __forceinline__ int binf(float s) {     // fine bins over [THR0,1)
    int b = (int)((s - THR0) * 65536.0f);
    if (b < 0) b = 0;
    if (b > BINS - 1) b = BINS - 1;
    return b;
}
__device__ __forceinline__ int binc(float s) {     // coarse bins (fallback)
    int b = (int)(s * (float)BINS);
    if (b < 0) b = 0;
    if (b > BINS - 1) b = BINS - 1;
    return b;
}
__device__ __forceinline__ unsigned long long below_mask(int x) {
    return (x == 0) ? 0ULL : ((~0ULL) >> (64 - x));
}
__device__ __forceinline__ unsigned long long mkkey(float s, unsigned int idx) {
    return ((unsigned long long)fkey(s) << 32) | (unsigned long long)(~idx);
}
__device__ __forceinline__ void push(int b, float s, unsigned int idx) {
    if (s >= THR0) {
        int p = atomicAdd(&g_cc[b], 1);
        if (p < CAP0) g_cand0[b][p] = mkkey(s, idx);
    }
}

// ============ L1: strided collect, 4 tiles (8 loads) in flight + fused flags =
__global__ void k_extract(const float* __restrict__ y) {
    int b = blockIdx.y;
    const float4* base4 = (const float4*)(y + (size_t)b * NBOX * NCH);
    int stride = gridDim.x * blockDim.x;
    int t = blockIdx.x * blockDim.x + threadIdx.x;

    // main loop: 4 tiles -> 8 independent LDG.128 before any dependent work
    for (; t + 3 * stride < NTILE; t += 4 * stride) {
        int t0 = t, t1 = t + stride, t2 = t + 2 * stride, t3 = t + 3 * stride;
        float4 a0 = __ldcs(&base4[11 * t0]);
        float4 c0 = __ldcs(&base4[11 * t0 + 5]);
        float4 a1 = __ldcs(&base4[11 * t1]);
        float4 c1 = __ldcs(&base4[11 * t1 + 5]);
        float4 a2 = __ldcs(&base4[11 * t2]);
        float4 c2 = __ldcs(&base4[11 * t2 + 5]);
        float4 a3 = __ldcs(&base4[11 * t3]);
        float4 c3 = __ldcs(&base4[11 * t3 + 5]);
        push(b, a0.y, (unsigned int)(2 * t0));
        push(b, c0.w, (unsigned int)(2 * t0 + 1));
        push(b, a1.y, (unsigned int)(2 * t1));
        push(b, c1.w, (unsigned int)(2 * t1 + 1));
        push(b, a2.y, (unsigned int)(2 * t2));
        push(b, c2.w, (unsigned int)(2 * t2 + 1));
        push(b, a3.y, (unsigned int)(2 * t3));
        push(b, c3.w, (unsigned int)(2 * t3 + 1));
    }
    // tail
    for (; t < NTILE; t += stride) {
        float4 a = __ldcs(&base4[11 * t]);
        float4 c = __ldcs(&base4[11 * t + 5]);
        push(b, a.y, (unsigned int)(2 * t));
        push(b, c.w, (unsigned int)(2 * t + 1));
    }

    // ---- fused flags: last block of this batch publishes m/fast, resets ----
    __syncthreads();
    if (threadIdx.x == 0) {
        __threadfence();
        int old = atomicAdd(&g_done[b], 1);
        if (old == gridDim.x - 1) {
            __threadfence();
            int cc = g_cc[b];
            g_m[b]    = (cc < CAP0) ? cc : CAP0;
            g_fast[b] = (cc >= NMS_MAX && cc <= CAP0) ? 1 : 0;
            g_cc[b]   = 0;
            g_done[b] = 0;
        }
    }
}

// ============ L2: candidate hist + cutoff + filter + sort + decode ===========
__global__ __launch_bounds__(1024, 1)
void k_sortdecode(const float* __restrict__ y) {
    __shared__ __align__(16) unsigned long long cand[SORTW];
    __shared__ unsigned int hist[BINS];
    __shared__ int s_m, s_cut;
    int b = blockIdx.x, tid = threadIdx.x, lane = tid & 31;
    int fast = g_fast[b];
    int cc = g_m[b];

    if (tid == 0) s_m = 0;
    cand[tid] = 0ULL;
    hist[tid] = 0u;
    __syncthreads();

    if (fast) {
        for (int i = tid; i < cc; i += 1024) {
            float s = fkey_inv((unsigned int)(g_cand0[b][i] >> 32));
            atomicAdd(&hist[binf(s)], 1u);
        }
    } else {
        const float* base = y + (size_t)b * NBOX * NCH + 1;
        for (int i = tid; i < NBOX; i += 1024) {
            float s = base[(size_t)i * NCH];
            atomicAdd(&hist[binc(s)], 1u);
        }
    }
    __syncthreads();

    if (tid < 32) {
        int cum = 0, cut = 0;
        for (int base = BINS - 32; base >= 0; base -= 32) {
            int p = (int)hist[base + 31 - lane];
#pragma unroll
            for (int o = 1; o < 32; o <<= 1) {
                int t = __shfl_up_sync(0xffffffffu, p, o);
                if (lane >= o) p += t;
            }
            unsigned ball = __ballot_sync(0xffffffffu, cum + p >= NMS_MAX);
            if (ball) { cut = base + 31 - (__ffs(ball) - 1); break; }
            cum += __shfl_sync(0xffffffffu, p, 31);
        }
        if (lane == 0) s_cut = cut;
    }
    __syncthreads();
    int cut = s_cut;

    if (fast) {
        for (int i = tid; i < cc; i += 1024) {
            unsigned long long k = g_cand0[b][i];
            float s = fkey_inv((unsigned int)(k >> 32));
            if (binf(s) >= cut) {
                int p = atomicAdd(&s_m, 1);
                if (p < SORTW) cand[p] = k;
            }
        }
    } else {
        const float* base = y + (size_t)b * NBOX * NCH + 1;
        for (int i = tid; i < NBOX; i += 1024) {
            float s = base[(size_t)i * NCH];
            if (binc(s) >= cut) {
                int p = atomicAdd(&s_m, 1);
                if (p < SORTW) cand[p] = mkkey(s, (unsigned int)i);
            }
        }
    }
    __syncthreads();
    int m = s_m; if (m > SORTW) m = SORTW;
    int n = 512; while (n < m) n <<= 1;

    unsigned long long v = (tid < n) ? cand[tid] : 0ULL;

    for (int k = 2; k <= n; k <<= 1) {
        for (int j = k >> 1; j > 0; j >>= 1) {
            bool keep_max = (((tid & j) == 0) == ((tid & k) == 0));
            unsigned long long o;
            if (j < 32) {
                o = __shfl_xor_sync(0xffffffffu, v, j);
            } else {
                cand[tid] = v;
                __syncthreads();
                o = cand[tid ^ j];
                __syncthreads();
            }
            unsigned long long mx = (v > o) ? v : o;
            unsigned long long mn = (v > o) ? o : v;
            v = keep_max ? mx : mn;
        }
    }

    if (tid < NMS_MAX) {
        float s = fkey_inv((unsigned int)(v >> 32));
        unsigned int idx = ~(unsigned int)(v & 0xffffffffu);
        if (idx >= NBOX) idx = 0;
        g_sc[b][tid] = s;
        g_sidx[b][tid] = (int)idx;
        const float* r = y + ((size_t)b * NBOX + idx) * NCH;
        float l0 = r[2], l1 = r[3], l2 = r[4], l3 = r[5];
        float dcx = r[14], dcy = r[15], dw = r[16], dh = r[17];
        float v0 = r[18], v1 = r[19], v2 = r[20], v3 = r[21];
        float cx = l0 * v0 * dw + dcx;
        float cy = l1 * v1 * dh + dcy;
        float w  = expf(l2 * v2) * dw;
        float h  = expf(l3 * v3) * dh;
        g_bx[b][tid*4+0] = (cx - w * 0.5f) * 384.0f;
        g_bx[b][tid*4+1] = (cy - h * 0.5f) * 384.0f;
        g_bx[b][tid*4+2] = (cx + w * 0.5f) * 384.0f;
        g_bx[b][tid*4+3] = (cy + h * 0.5f) * 384.0f;
    }
}

// ============ L3: fused lazy-IoU + early-exit greedy + output ================
__global__ __launch_bounds__(512, 1)
void k_nms(const float* __restrict__ y, float* __restrict__ out) {
    __shared__ __align__(16) float4 bxs4[NMS_MAX];
    __shared__ float scs[NMS_MAX];
    __shared__ __align__(8) unsigned short ovb16[64 * 28];
    __shared__ unsigned long long keepw[MASKW];
    __shared__ int sel[NUM_PRED], selk[NUM_PRED];
    __shared__ int pp[MASKW + 1];
    __shared__ int s_stop, s_cnt;

    int b = blockIdx.x, tid = threadIdx.x;
    const float4* src = (const float4*)g_bx[b];
    for (int i = tid; i < NMS_MAX; i += 512) { bxs4[i] = src[i]; scs[i] = g_sc[b][i]; }
    if (tid < MASKW) keepw[tid] = 0ULL;
    if (tid == 0) { s_stop = 0; s_cnt = 0; }
    __syncthreads();

    for (int blk = 0; blk < MASKW; ++blk) {
        int rbase = blk * 64;
        int nrows = NMS_MAX - rbase; if (nrows > 64) nrows = 64;
        int nw16  = (blk + 1) * 4;
        int pairs = nrows * nw16;

        for (int p = tid; p < pairs; p += 512) {
            int r   = p / nw16;
            int w16 = p - r * nw16;
            int j0  = w16 * 16;
            unsigned int m = 0;
            if (j0 < NMS_MAX) {
                float4 A = bxs4[rbase + r];
                float areai = (A.z - A.x) * (A.w - A.y);
#pragma unroll 4
                for (int jj = 0; jj < 16; ++jj) {
                    int j = j0 + jj;
                    if (j < NMS_MAX) {
                        float4 B = bxs4[j];
                        float lt0 = fmaxf(A.x, B.x), lt1 = fmaxf(A.y, B.y);
                        float rb0 = fminf(A.z, B.z), rb1 = fminf(A.w, B.w);
                        float w0 = fmaxf(rb0 - lt0, 0.0f);
                        float w1 = fmaxf(rb1 - lt1, 0.0f);
                        float inter = w0 * w1;
                        float areaj = (B.z - B.x) * (B.w - B.y);
                        float uni = areai + areaj - inter;
                        if (inter / fmaxf(uni, 1e-8f) > 0.45f) m |= (1u << jj);
                    }
                }
            }
            ovb16[r * 28 + w16] = (unsigned short)m;
        }
        __syncthreads();

        if (tid < 32) {
            int t = tid;
            const unsigned long long* ovr = (const unsigned long long*)ovb16;
            unsigned long long rlo[MASKW], rhi[MASKW];
            float slo = 0.0f, shi = 0.0f;
            int ilo = rbase + t, ihi = ilo + 32;
#pragma unroll
            for (int w = 0; w < MASKW; ++w) {
                rlo[w] = (t < nrows)      ? ovr[t * 7 + w]        : 0ULL;
                rhi[w] = (t + 32 < nrows) ? ovr[(t + 32) * 7 + w] : 0ULL;
            }
            if (ilo < NMS_MAX) slo = scs[ilo];
            if (ihi < NMS_MAX) shi = scs[ihi];
            unsigned long long hlo = 0ULL, hhi = 0ULL;
#pragma unroll
            for (int w = 0; w < MASKW; ++w) {
                hlo |= rlo[w] & keepw[w];
                hhi |= rhi[w] & keepw[w];
            }
            bool oklo = (ilo < NMS_MAX) && (slo > 0.01f) && (hlo == 0ULL);
            bool okhi = (ihi < NMS_MAX) && (shi > 0.01f) && (hhi == 0ULL);
            unsigned blo = __ballot_sync(0xffffffffu, oklo);
            unsigned bhi = __ballot_sync(0xffffffffu, okhi);
            unsigned long long K = (unsigned long long)blo |
                                   ((unsigned long long)bhi << 32);
            unsigned long long Mlo = rlo[blk] & below_mask(t);
            unsigned long long Mhi = rhi[blk] & below_mask(t + 32);
            while (true) {
                bool badlo = ((K >> t) & 1ULL) && (Mlo & K);
                bool badhi = ((K >> (t + 32)) & 1ULL) && (Mhi & K);
                unsigned bl = __ballot_sync(0xffffffffu, badlo);
                unsigned bh = __ballot_sync(0xffffffffu, badhi);
                unsigned long long bad = (unsigned long long)bl |
                                         ((unsigned long long)bh << 32);
                if (!bad) break;
                K &= ~(bad & (0ULL - bad));
            }
            if (t == 0) {
                keepw[blk] = K;
                s_cnt += __popcll(K);
                if (s_cnt >= NUM_PRED) s_stop = 1;
            }
        }
        __syncthreads();
        if (s_stop) break;
    }

    if (tid == 0) {
        pp[0] = 0;
#pragma unroll
        for (int w = 0; w < MASKW; ++w) pp[w + 1] = pp[w] + __popcll(keepw[w]);
    }
    __syncthreads();

    if (tid < NMS_MAX) {
        int w = tid >> 6, bit = tid & 63;
        unsigned long long below = keepw[w] & below_mask(bit);
        int keptBefore = pp[w] + __popcll(below);
        bool kept = (keepw[w] >> bit) & 1ULL;
        int K = pp[MASKW];
        if (kept) {
            if (keptBefore < NUM_PRED) { sel[keptBefore] = tid; selk[keptBefore] = 1; }
        } else {
            int r = K + (tid - keptBefore);
            if (r < NUM_PRED) { sel[r] = tid; selk[r] = 0; }
        }
    }
    __syncthreads();

    if (tid < NUM_PRED) {
        int i = sel[tid];
        float* o = out + ((size_t)b * NUM_PRED + tid) * 13;
        float4 A = bxs4[i];
        o[0] = selk[tid] ? scs[i] : -1.0f;
        o[1] = A.x; o[2] = A.y; o[3] = A.z; o[4] = A.w;
        const float* r = y + ((size_t)b * NBOX + g_sidx[b][i]) * NCH;
        float dcx = r[14], dcy = r[15], dw = r[16], dh = r[17];
        float v0 = r[18], v1 = r[19];
        float dqx[4] = {dcx - dw*0.5f, dcx + dw*0.5f, dcx + dw*0.5f, dcx - dw*0.5f};
        float dqy[4] = {dcy - dh*0.5f, dcy - dh*0.5f, dcy + dh*0.5f, dcy + dh*0.5f};
#pragma unroll
        for (int k = 0; k < 4; ++k) {
            float qx = dqx[k] + r[6 + 2*k] * v0 * dw;
            float qy = dqy[k] + r[7 + 2*k] * v1 * dh;
            o[5 + 2*k]     = qx * 384.0f;
            o[5 + 2*k + 1] = qy * 384.0f;
        }
    }
}

// ---------------- launch ---------------------------------------------------
extern "C" void kernel_launch(void* const* d_in, const int* in_sizes, int n_in,
                              void* d_out, int out_size) {
    const float* y = (const float*)d_in[0];
    float* out = (float*)d_out;
    k_extract<<<dim3(HBLK, BATCH), 256>>>(y);
    k_sortdecode<<<BATCH, 1024>>>(y);
    k_nms<<<BATCH, 512>>>(y, out);
}

// round 16
// speedup vs baseline: 1.0326x; 1.0326x over previous
#include <cuda_runtime.h>
#include <math.h>

#define BATCH    16
#define NBOX     120000
#define NCH      22
#define NMS_MAX  400
#define NUM_PRED 10
#define BINS     1024
#define HBLK     64
#define CAP0     4096
#define THR0     0.984375f
#define SORTW    1024
#define MASKW    7
#define NTILE    (NBOX / 2)

// ---------------- scratch ----------------------------------------------------
__device__ int                g_cc[BATCH];     // zero-init; extract last block resets
__device__ int                g_done[BATCH];
__device__ int                g_m[BATCH];
__device__ int                g_fast[BATCH];
__device__ unsigned long long g_cand0[BATCH][CAP0];

__device__ __forceinline__ unsigned int fkey(float f) {
    unsigned int u = __float_as_uint(f);
    return (u & 0x80000000u) ? ~u : (u | 0x80000000u);
}
__device__ __forceinline__ float fkey_inv(unsigned int k) {
    unsigned int u = (k & 0x80000000u) ? (k & 0x7fffffffu) : ~k;
    return __uint_as_float(u);
}
__device__ __forceinline__ int binf(float s) {     // fine bins over [THR0,1)
    int b = (int)((s - THR0) * 65536.0f);
    if (b < 0) b = 0;
    if (b > BINS - 1) b = BINS - 1;
    return b;
}
__device__ __forceinline__ int binc(float s) {     // coarse bins (fallback)
    int b = (int)(s * (float)BINS);
    if (b < 0) b = 0;
    if (b > BINS - 1) b = BINS - 1;
    return b;
}
__device__ __forceinline__ unsigned long long below_mask(int x) {
    return (x == 0) ? 0ULL : ((~0ULL) >> (64 - x));
}
__device__ __forceinline__ unsigned long long mkkey(float s, unsigned int idx) {
    return ((unsigned long long)fkey(s) << 32) | (unsigned long long)(~idx);
}

// ============ L1: strided threshold collect (2-tile) + fused flags ===========
__global__ void k_extract(const float* __restrict__ y) {
    int b = blockIdx.y;
    const float4* base4 = (const float4*)(y + (size_t)b * NBOX * NCH);
    int stride = gridDim.x * blockDim.x;
    int t = blockIdx.x * blockDim.x + threadIdx.x;
    for (; t + stride < NTILE; t += 2 * stride) {
        int t2 = t + stride;
        float4 a0 = __ldcs(&base4[11 * t]);
        float4 c0 = __ldcs(&base4[11 * t + 5]);
        float4 a1 = __ldcs(&base4[11 * t2]);
        float4 c1 = __ldcs(&base4[11 * t2 + 5]);
        float s00 = a0.y, s01 = c0.w, s10 = a1.y, s11 = c1.w;
        if (s00 >= THR0) {
            int p = atomicAdd(&g_cc[b], 1);
            if (p < CAP0) g_cand0[b][p] = mkkey(s00, (unsigned int)(2 * t));
        }
        if (s01 >= THR0) {
            int p = atomicAdd(&g_cc[b], 1);
            if (p < CAP0) g_cand0[b][p] = mkkey(s01, (unsigned int)(2 * t + 1));
        }
        if (s10 >= THR0) {
            int p = atomicAdd(&g_cc[b], 1);
            if (p < CAP0) g_cand0[b][p] = mkkey(s10, (unsigned int)(2 * t2));
        }
        if (s11 >= THR0) {
            int p = atomicAdd(&g_cc[b], 1);
            if (p < CAP0) g_cand0[b][p] = mkkey(s11, (unsigned int)(2 * t2 + 1));
        }
    }
    if (t < NTILE) {
        float4 a = __ldcs(&base4[11 * t]);
        float4 c = __ldcs(&base4[11 * t + 5]);
        float s0 = a.y, s1 = c.w;
        if (s0 >= THR0) {
            int p = atomicAdd(&g_cc[b], 1);
            if (p < CAP0) g_cand0[b][p] = mkkey(s0, (unsigned int)(2 * t));
        }
        if (s1 >= THR0) {
            int p = atomicAdd(&g_cc[b], 1);
            if (p < CAP0) g_cand0[b][p] = mkkey(s1, (unsigned int)(2 * t + 1));
        }
    }

    __syncthreads();
    if (threadIdx.x == 0) {
        __threadfence();
        int old = atomicAdd(&g_done[b], 1);
        if (old == gridDim.x - 1) {
            __threadfence();
            int cc = g_cc[b];
            g_m[b]    = (cc < CAP0) ? cc : CAP0;
            g_fast[b] = (cc >= NMS_MAX && cc <= CAP0) ? 1 : 0;
            g_cc[b]   = 0;
            g_done[b] = 0;
        }
    }
}

// ============ L2: fused sort+decode+lazy-IoU+greedy+output ===================
// Phase 1 shared (dies after sort): cand u64[1024] 8KB + hist u32[1024] 4KB
// Phase 2 shared: bxs4 f4[400] 6.4KB + scs f32[400] 1.6KB + ovb16 3.5KB
// Overlay phase-2 bxs4/scs on phase-1 buffers via a union block.
struct TailShared {
    union {
        struct {
            unsigned long long cand[SORTW];   // 8192 B
            unsigned int hist[BINS];          // 4096 B
        } p1;
        struct {
            float4 bxs4[NMS_MAX];             // 6400 B
            float  scs[NMS_MAX];              // 1600 B
            unsigned short ovb16[64 * 28];    // 3584 B
        } p2;
    } u;
};

__global__ __launch_bounds__(1024, 1)
void k_tail(const float* __restrict__ y, float* __restrict__ out) {
    __shared__ __align__(16) TailShared S;
    __shared__ unsigned long long keepw[MASKW];
    __shared__ int sel[NUM_PRED], selk[NUM_PRED];
    __shared__ int pp[MASKW + 1];
    __shared__ int s_m, s_cut, s_stop, s_cnt;
    // decode results must survive the phase-1 -> phase-2 overlay switch:
    __shared__ float dbx[NMS_MAX * 4];
    __shared__ float dsc[NMS_MAX];
    __shared__ int   dsidx[NMS_MAX];

    int b = blockIdx.x, tid = threadIdx.x, lane = tid & 31;
    int fast = g_fast[b];
    int cc = g_m[b];

    if (tid == 0) { s_m = 0; s_stop = 0; s_cnt = 0; }
    S.u.p1.cand[tid] = 0ULL;
    S.u.p1.hist[tid] = 0u;
    if (tid < MASKW) keepw[tid] = 0ULL;
    __syncthreads();

    // --- pass A: histogram ---
    if (fast) {
        for (int i = tid; i < cc; i += 1024) {
            float s = fkey_inv((unsigned int)(g_cand0[b][i] >> 32));
            atomicAdd(&S.u.p1.hist[binf(s)], 1u);
        }
    } else {
        const float* base = y + (size_t)b * NBOX * NCH + 1;
        for (int i = tid; i < NBOX; i += 1024) {
            float s = base[(size_t)i * NCH];
            atomicAdd(&S.u.p1.hist[binc(s)], 1u);
        }
    }
    __syncthreads();

    // --- cutoff ---
    if (tid < 32) {
        int cum = 0, cut = 0;
        for (int base = BINS - 32; base >= 0; base -= 32) {
            int p = (int)S.u.p1.hist[base + 31 - lane];
#pragma unroll
            for (int o = 1; o < 32; o <<= 1) {
                int t = __shfl_up_sync(0xffffffffu, p, o);
                if (lane >= o) p += t;
            }
            unsigned ball = __ballot_sync(0xffffffffu, cum + p >= NMS_MAX);
            if (ball) { cut = base + 31 - (__ffs(ball) - 1); break; }
            cum += __shfl_sync(0xffffffffu, p, 31);
        }
        if (lane == 0) s_cut = cut;
    }
    __syncthreads();
    int cut = s_cut;

    // --- pass B: filter ---
    if (fast) {
        for (int i = tid; i < cc; i += 1024) {
            unsigned long long k = g_cand0[b][i];
            float s = fkey_inv((unsigned int)(k >> 32));
            if (binf(s) >= cut) {
                int p = atomicAdd(&s_m, 1);
                if (p < SORTW) S.u.p1.cand[p] = k;
            }
        }
    } else {
        const float* base = y + (size_t)b * NBOX * NCH + 1;
        for (int i = tid; i < NBOX; i += 1024) {
            float s = base[(size_t)i * NCH];
            if (binc(s) >= cut) {
                int p = atomicAdd(&s_m, 1);
                if (p < SORTW) S.u.p1.cand[p] = mkkey(s, (unsigned int)i);
            }
        }
    }
    __syncthreads();
    int m = s_m; if (m > SORTW) m = SORTW;
    int n = 512; while (n < m) n <<= 1;

    unsigned long long v = (tid < n) ? S.u.p1.cand[tid] : 0ULL;

    // --- hybrid bitonic sort (descending) ---
    for (int k = 2; k <= n; k <<= 1) {
        for (int j = k >> 1; j > 0; j >>= 1) {
            bool keep_max = (((tid & j) == 0) == ((tid & k) == 0));
            unsigned long long o;
            if (j < 32) {
                o = __shfl_xor_sync(0xffffffffu, v, j);
            } else {
                S.u.p1.cand[tid] = v;
                __syncthreads();
                o = S.u.p1.cand[tid ^ j];
                __syncthreads();
            }
            unsigned long long mx = (v > o) ? v : o;
            unsigned long long mn = (v > o) ? o : v;
            v = keep_max ? mx : mn;
        }
    }

    // --- decode top-400 into overlay-safe buffers ---
    if (tid < NMS_MAX) {
        float s = fkey_inv((unsigned int)(v >> 32));
        unsigned int idx = ~(unsigned int)(v & 0xffffffffu);
        if (idx >= NBOX) idx = 0;
        dsc[tid] = s;
        dsidx[tid] = (int)idx;
        const float* r = y + ((size_t)b * NBOX + idx) * NCH;
        float l0 = r[2], l1 = r[3], l2 = r[4], l3 = r[5];
        float dcx = r[14], dcy = r[15], dw = r[16], dh = r[17];
        float v0 = r[18], v1 = r[19], v2 = r[20], v3 = r[21];
        float cx = l0 * v0 * dw + dcx;
        float cy = l1 * v1 * dh + dcy;
        float w  = expf(l2 * v2) * dw;
        float h  = expf(l3 * v3) * dh;
        dbx[tid*4+0] = (cx - w * 0.5f) * 384.0f;
        dbx[tid*4+1] = (cy - h * 0.5f) * 384.0f;
        dbx[tid*4+2] = (cx + w * 0.5f) * 384.0f;
        dbx[tid*4+3] = (cy + h * 0.5f) * 384.0f;
    }
    __syncthreads();          // phase-1 buffers dead; switch to phase-2 view

    // copy decode results into the (overlaid) phase-2 arrays
    for (int i = tid; i < NMS_MAX; i += 1024) {
        S.u.p2.bxs4[i] = make_float4(dbx[i*4+0], dbx[i*4+1], dbx[i*4+2], dbx[i*4+3]);
        S.u.p2.scs[i] = dsc[i];
    }
    __syncthreads();

    // --- lazy-IoU + early-exit greedy ---
    for (int blk = 0; blk < MASKW; ++blk) {
        int rbase = blk * 64;
        int nrows = NMS_MAX - rbase; if (nrows > 64) nrows = 64;
        int nw16  = (blk + 1) * 4;
        int pairs = nrows * nw16;

        for (int p = tid; p < pairs; p += 1024) {
            int r   = p / nw16;
            int w16 = p - r * nw16;
            int j0  = w16 * 16;
            unsigned int mm = 0;
            if (j0 < NMS_MAX) {
                float4 A = S.u.p2.bxs4[rbase + r];
                float areai = (A.z - A.x) * (A.w - A.y);
#pragma unroll 4
                for (int jj = 0; jj < 16; ++jj) {
                    int j = j0 + jj;
                    if (j < NMS_MAX) {
                        float4 B = S.u.p2.bxs4[j];
                        float lt0 = fmaxf(A.x, B.x), lt1 = fmaxf(A.y, B.y);
                        float rb0 = fminf(A.z, B.z), rb1 = fminf(A.w, B.w);
                        float w0 = fmaxf(rb0 - lt0, 0.0f);
                        float w1 = fmaxf(rb1 - lt1, 0.0f);
                        float inter = w0 * w1;
                        float areaj = (B.z - B.x) * (B.w - B.y);
                        float uni = areai + areaj - inter;
                        if (inter / fmaxf(uni, 1e-8f) > 0.45f) mm |= (1u << jj);
                    }
                }
            }
            S.u.p2.ovb16[r * 28 + w16] = (unsigned short)mm;
        }
        __syncthreads();

        if (tid < 32) {
            int t = tid;
            const unsigned long long* ovr = (const unsigned long long*)S.u.p2.ovb16;
            unsigned long long rlo[MASKW], rhi[MASKW];
            float slo = 0.0f, shi = 0.0f;
            int ilo = rbase + t, ihi = ilo + 32;
#pragma unroll
            for (int w = 0; w < MASKW; ++w) {
                rlo[w] = (t < nrows)      ? ovr[t * 7 + w]        : 0ULL;
                rhi[w] = (t + 32 < nrows) ? ovr[(t + 32) * 7 + w] : 0ULL;
            }
            if (ilo < NMS_MAX) slo = S.u.p2.scs[ilo];
            if (ihi < NMS_MAX) shi = S.u.p2.scs[ihi];
            unsigned long long hlo = 0ULL, hhi = 0ULL;
#pragma unroll
            for (int w = 0; w < MASKW; ++w) {
                hlo |= rlo[w] & keepw[w];
                hhi |= rhi[w] & keepw[w];
            }
            bool oklo = (ilo < NMS_MAX) && (slo > 0.01f) && (hlo == 0ULL);
            bool okhi = (ihi < NMS_MAX) && (shi > 0.01f) && (hhi == 0ULL);
            unsigned blo = __ballot_sync(0xffffffffu, oklo);
            unsigned bhi = __ballot_sync(0xffffffffu, okhi);
            unsigned long long K = (unsigned long long)blo |
                                   ((unsigned long long)bhi << 32);
            unsigned long long Mlo = rlo[blk] & below_mask(t);
            unsigned long long Mhi = rhi[blk] & below_mask(t + 32);
            while (true) {
                bool badlo = ((K >> t) & 1ULL) && (Mlo & K);
                bool badhi = ((K >> (t + 32)) & 1ULL) && (Mhi & K);
                unsigned bl = __ballot_sync(0xffffffffu, badlo);
                unsigned bh = __ballot_sync(0xffffffffu, badhi);
                unsigned long long bad = (unsigned long long)bl |
                                         ((unsigned long long)bh << 32);
                if (!bad) break;
                K &= ~(bad & (0ULL - bad));
            }
            if (t == 0) {
                keepw[blk] = K;
                s_cnt += __popcll(K);
                if (s_cnt >= NUM_PRED) s_stop = 1;
            }
        }
        __syncthreads();
        if (s_stop) break;
    }

    if (tid == 0) {
        pp[0] = 0;
#pragma unroll
        for (int w = 0; w < MASKW; ++w) pp[w + 1] = pp[w] + __popcll(keepw[w]);
    }
    __syncthreads();

    if (tid < NMS_MAX) {
        int w = tid >> 6, bit = tid & 63;
        unsigned long long below = keepw[w] & below_mask(bit);
        int keptBefore = pp[w] + __popcll(below);
        bool kept = (keepw[w] >> bit) & 1ULL;
        int K = pp[MASKW];
        if (kept) {
            if (keptBefore < NUM_PRED) { sel[keptBefore] = tid; selk[keptBefore] = 1; }
        } else {
            int r = K + (tid - keptBefore);
            if (r < NUM_PRED) { sel[r] = tid; selk[r] = 0; }
        }
    }
    __syncthreads();

    if (tid < NUM_PRED) {
        int i = sel[tid];
        float* o = out + ((size_t)b * NUM_PRED + tid) * 13;
        float4 A = S.u.p2.bxs4[i];
        o[0] = selk[tid] ? S.u.p2.scs[i] : -1.0f;
        o[1] = A.x; o[2] = A.y; o[3] = A.z; o[4] = A.w;
        const float* r = y + ((size_t)b * NBOX + dsidx[i]) * NCH;
        float dcx = r[14], dcy = r[15], dw = r[16], dh = r[17];
        float v0 = r[18], v1 = r[19];
        float dqx[4] = {dcx - dw*0.5f, dcx + dw*0.5f, dcx + dw*0.5f, dcx - dw*0.5f};
        float dqy[4] = {dcy - dh*0.5f, dcy - dh*0.5f, dcy + dh*0.5f, dcy + dh*0.5f};
#pragma unroll
        for (int k = 0; k < 4; ++k) {
            float qx = dqx[k] + r[6 + 2*k] * v0 * dw;
            float qy = dqy[k] + r[7 + 2*k] * v1 * dh;
            o[5 + 2*k]     = qx * 384.0f;
            o[5 + 2*k + 1] = qy * 384.0f;
        }
    }
}

// ---------------- launch ---------------------------------------------------
extern "C" void kernel_launch(void* const* d_in, const int* in_sizes, int n_in,
                              void* d_out, int out_size) {
    const float* y = (const float*)d_in[0];
    float* out = (float*)d_out;
    k_extract<<<dim3(HBLK, BATCH), 256>>>(y);
    k_tail<<<BATCH, 1024>>>(y, out);
}

// round 17
// speedup vs baseline: 1.1182x; 1.0829x over previous
#include <cuda_runtime.h>
#include <math.h>

#define BATCH    16
#define NBOX     120000
#define NCH      22
#define NMS_MAX  400
#define NUM_PRED 10
#define BINS     1024
#define HBLK     64
#define CAP0     4096
#define THR0     0.984375f
#define SORTW    1024
#define MASKW    7
#define NTILE    (NBOX / 2)

// ---------------- scratch ----------------------------------------------------
__device__ int                g_cc[BATCH];     // zero-init; extract last block resets
__device__ int                g_done[BATCH];
__device__ int                g_m[BATCH];
__device__ int                g_fast[BATCH];
__device__ unsigned long long g_cand0[BATCH][CAP0];

__device__ __forceinline__ unsigned int fkey(float f) {
    unsigned int u = __float_as_uint(f);
    return (u & 0x80000000u) ? ~u : (u | 0x80000000u);
}
__device__ __forceinline__ float fkey_inv(unsigned int k) {
    unsigned int u = (k & 0x80000000u) ? (k & 0x7fffffffu) : ~k;
    return __uint_as_float(u);
}
__device__ __forceinline__ int binf(float s) {
    int b = (int)((s - THR0) * 65536.0f);
    if (b < 0) b = 0;
    if (b > BINS - 1) b = BINS - 1;
    return b;
}
__device__ __forceinline__ int binc(float s) {
    int b = (int)(s * (float)BINS);
    if (b < 0) b = 0;
    if (b > BINS - 1) b = BINS - 1;
    return b;
}
__device__ __forceinline__ unsigned long long below_mask(int x) {
    return (x == 0) ? 0ULL : ((~0ULL) >> (64 - x));
}
__device__ __forceinline__ unsigned long long mkkey(float s, unsigned int idx) {
    return ((unsigned long long)fkey(s) << 32) | (unsigned long long)(~idx);
}

// IoU predicate on decoded corner boxes
__device__ __forceinline__ bool iou_gt(float4 A, float areai, float4 B) {
    float lt0 = fmaxf(A.x, B.x), lt1 = fmaxf(A.y, B.y);
    float rb0 = fminf(A.z, B.z), rb1 = fminf(A.w, B.w);
    float w0 = fmaxf(rb0 - lt0, 0.0f);
    float w1 = fmaxf(rb1 - lt1, 0.0f);
    float inter = w0 * w1;
    float areaj = (B.z - B.x) * (B.w - B.y);
    float uni = areai + areaj - inter;
    return inter / fmaxf(uni, 1e-8f) > 0.45f;
}

// decode one row of y -> corner box
__device__ __forceinline__ float4 decode_box(const float* r) {
    float l0 = r[2], l1 = r[3], l2 = r[4], l3 = r[5];
    float dcx = r[14], dcy = r[15], dw = r[16], dh = r[17];
    float v0 = r[18], v1 = r[19], v2 = r[20], v3 = r[21];
    float cx = l0 * v0 * dw + dcx;
    float cy = l1 * v1 * dh + dcy;
    float w  = expf(l2 * v2) * dw;
    float h  = expf(l3 * v3) * dh;
    return make_float4((cx - w * 0.5f) * 384.0f, (cy - h * 0.5f) * 384.0f,
                       (cx + w * 0.5f) * 384.0f, (cy + h * 0.5f) * 384.0f);
}

// write one output row [score, box4, quad8]
__device__ __forceinline__ void write_row(float* o, float score, float4 A,
                                          const float* r) {
    o[0] = score;
    o[1] = A.x; o[2] = A.y; o[3] = A.z; o[4] = A.w;
    float dcx = r[14], dcy = r[15], dw = r[16], dh = r[17];
    float v0 = r[18], v1 = r[19];
    float dqx[4] = {dcx - dw*0.5f, dcx + dw*0.5f, dcx + dw*0.5f, dcx - dw*0.5f};
    float dqy[4] = {dcy - dh*0.5f, dcy - dh*0.5f, dcy + dh*0.5f, dcy + dh*0.5f};
#pragma unroll
    for (int k = 0; k < 4; ++k) {
        o[5 + 2*k]     = (dqx[k] + r[6 + 2*k] * v0 * dw) * 384.0f;
        o[5 + 2*k + 1] = (dqy[k] + r[7 + 2*k] * v1 * dh) * 384.0f;
    }
}

// ============ L1: strided threshold collect (2-tile) + fused flags ===========
__global__ void k_extract(const float* __restrict__ y) {
    int b = blockIdx.y;
    const float4* base4 = (const float4*)(y + (size_t)b * NBOX * NCH);
    int stride = gridDim.x * blockDim.x;
    int t = blockIdx.x * blockDim.x + threadIdx.x;
    for (; t + stride < NTILE; t += 2 * stride) {
        int t2 = t + stride;
        float4 a0 = __ldcs(&base4[11 * t]);
        float4 c0 = __ldcs(&base4[11 * t + 5]);
        float4 a1 = __ldcs(&base4[11 * t2]);
        float4 c1 = __ldcs(&base4[11 * t2 + 5]);
        float s00 = a0.y, s01 = c0.w, s10 = a1.y, s11 = c1.w;
        if (s00 >= THR0) {
            int p = atomicAdd(&g_cc[b], 1);
            if (p < CAP0) g_cand0[b][p] = mkkey(s00, (unsigned int)(2 * t));
        }
        if (s01 >= THR0) {
            int p = atomicAdd(&g_cc[b], 1);
            if (p < CAP0) g_cand0[b][p] = mkkey(s01, (unsigned int)(2 * t + 1));
        }
        if (s10 >= THR0) {
            int p = atomicAdd(&g_cc[b], 1);
            if (p < CAP0) g_cand0[b][p] = mkkey(s10, (unsigned int)(2 * t2));
        }
        if (s11 >= THR0) {
            int p = atomicAdd(&g_cc[b], 1);
            if (p < CAP0) g_cand0[b][p] = mkkey(s11, (unsigned int)(2 * t2 + 1));
        }
    }
    if (t < NTILE) {
        float4 a = __ldcs(&base4[11 * t]);
        float4 c = __ldcs(&base4[11 * t + 5]);
        float s0 = a.y, s1 = c.w;
        if (s0 >= THR0) {
            int p = atomicAdd(&g_cc[b], 1);
            if (p < CAP0) g_cand0[b][p] = mkkey(s0, (unsigned int)(2 * t));
        }
        if (s1 >= THR0) {
            int p = atomicAdd(&g_cc[b], 1);
            if (p < CAP0) g_cand0[b][p] = mkkey(s1, (unsigned int)(2 * t + 1));
        }
    }

    __syncthreads();
    if (threadIdx.x == 0) {
        __threadfence();
        int old = atomicAdd(&g_done[b], 1);
        if (old == gridDim.x - 1) {
            __threadfence();
            int cc = g_cc[b];
            g_m[b]    = (cc < CAP0) ? cc : CAP0;
            g_fast[b] = (cc >= NMS_MAX && cc <= CAP0) ? 1 : 0;
            g_cc[b]   = 0;
            g_done[b] = 0;
        }
    }
}

// ============ L2: fused tail with 64-wide fast path ==========================
struct TailShared {
    union {
        struct {
            unsigned long long cand[SORTW];   // 8192 B
            unsigned int hist[BINS];          // 4096 B
        } p1;
        struct {
            float4 bxs4[NMS_MAX];             // 6400 B
            float  scs[NMS_MAX];              // 1600 B
            unsigned short ovb16[64 * 28];    // 3584 B
        } p2;
    } u;
};

__global__ __launch_bounds__(1024, 1)
void k_tail(const float* __restrict__ y, float* __restrict__ out) {
    __shared__ __align__(16) TailShared S;
    __shared__ unsigned long long keepw[MASKW];
    __shared__ int sel[NUM_PRED];
    __shared__ int selk[NUM_PRED];
    __shared__ int pp[MASKW + 1];
    __shared__ int s_m, s_cut, s_stop, s_cnt;
    // 64-wide fast-path buffers (never alias the union)
    __shared__ __align__(16) unsigned long long cand64[128];
    __shared__ __align__(16) float4 bx64[64];
    __shared__ float sc64[64];
    __shared__ int   sidx64[64];
    __shared__ __align__(8) unsigned short ov64w[64 * 4];  // = u64[64]
    __shared__ unsigned long long s_k64;
    __shared__ int s_m64, s_cut64, s_cnt64;
    // fallback decode buffers (survive the union-overlay switch)
    __shared__ float dbx[NMS_MAX * 4];
    __shared__ float dsc[NMS_MAX];
    __shared__ int   dsidx[NMS_MAX];

    int b = blockIdx.x, tid = threadIdx.x, lane = tid & 31;
    int fast = g_fast[b];
    int cc = g_m[b];

    if (tid == 0) { s_m = 0; s_stop = 0; s_cnt = 0; s_m64 = 0; s_cnt64 = 0; }
    S.u.p1.cand[tid] = 0ULL;
    S.u.p1.hist[tid] = 0u;
    if (tid < MASKW) keepw[tid] = 0ULL;
    if (tid < 128) cand64[tid] = 0ULL;
    __syncthreads();

    // --- build histogram (shared by 64-path and fallback) ---
    if (fast) {
        for (int i = tid; i < cc; i += 1024) {
            float s = fkey_inv((unsigned int)(g_cand0[b][i] >> 32));
            atomicAdd(&S.u.p1.hist[binf(s)], 1u);
        }
    } else {
        const float* base = y + (size_t)b * NBOX * NCH + 1;
        for (int i = tid; i < NBOX; i += 1024) {
            float s = base[(size_t)i * NCH];
            atomicAdd(&S.u.p1.hist[binc(s)], 1u);
        }
    }
    __syncthreads();

    // --- cutoff for target 64 (fast only) and target 400 ---
    if (tid < 32) {
        int cum = 0, cut64 = 0, cut400 = 0;
        bool got64 = false;
        for (int base = BINS - 32; base >= 0; base -= 32) {
            int p = (int)S.u.p1.hist[base + 31 - lane];
#pragma unroll
            for (int o = 1; o < 32; o <<= 1) {
                int t2 = __shfl_up_sync(0xffffffffu, p, o);
                if (lane >= o) p += t2;
            }
            if (!got64) {
                unsigned ball = __ballot_sync(0xffffffffu, cum + p >= 64);
                if (ball) { cut64 = base + 31 - (__ffs(ball) - 1); got64 = true; }
            }
            unsigned ball4 = __ballot_sync(0xffffffffu, cum + p >= NMS_MAX);
            if (ball4) { cut400 = base + 31 - (__ffs(ball4) - 1); break; }
            cum += __shfl_sync(0xffffffffu, p, 31);
        }
        if (lane == 0) { s_cut64 = cut64; s_cut = cut400; }
    }
    __syncthreads();

    // =================== 64-wide fast path ===================
    bool did64 = false;
    if (fast) {
        int cut64 = s_cut64;
        for (int i = tid; i < cc; i += 1024) {
            unsigned long long k = g_cand0[b][i];
            float s = fkey_inv((unsigned int)(k >> 32));
            if (binf(s) >= cut64) {
                int p = atomicAdd(&s_m64, 1);
                if (p < 128) cand64[p] = k;
            }
        }
        __syncthreads();
        int m64 = s_m64;
        if (m64 <= 128) {
            did64 = true;
            int n64 = 64; while (n64 < m64) n64 <<= 1;   // 64 or 128
            unsigned long long v = (tid < n64) ? cand64[tid] : 0ULL;
            for (int k = 2; k <= n64; k <<= 1) {
                for (int j = k >> 1; j > 0; j >>= 1) {
                    bool keep_max = (((tid & j) == 0) == ((tid & k) == 0));
                    unsigned long long o;
                    if (j < 32) {
                        o = __shfl_xor_sync(0xffffffffu, v, j);
                    } else {
                        if (tid < n64) cand64[tid] = v;
                        __syncthreads();
                        o = (tid < n64) ? cand64[tid ^ j] : 0ULL;
                        __syncthreads();
                    }
                    unsigned long long mx = (v > o) ? v : o;
                    unsigned long long mn = (v > o) ? o : v;
                    v = keep_max ? mx : mn;
                }
            }
            // decode top-64
            if (tid < 64) {
                float s = fkey_inv((unsigned int)(v >> 32));
                unsigned int idx = ~(unsigned int)(v & 0xffffffffu);
                if (idx >= NBOX) idx = 0;
                sc64[tid] = s;
                sidx64[tid] = (int)idx;
                bx64[tid] = decode_box(y + ((size_t)b * NBOX + idx) * NCH);
            }
            __syncthreads();
            // IoU 64x64: 256 u16 jobs
            if (tid < 256) {
                int r = tid >> 2, w16 = tid & 3;
                int j0 = w16 * 16;
                float4 A = bx64[r];
                float areai = (A.z - A.x) * (A.w - A.y);
                unsigned int m = 0;
#pragma unroll 4
                for (int jj = 0; jj < 16; ++jj) {
                    if (iou_gt(A, areai, bx64[j0 + jj])) m |= (1u << jj);
                }
                ov64w[r * 4 + w16] = (unsigned short)m;
            }
            __syncthreads();
            // single-word greedy (warp 0)
            if (tid < 32) {
                int t = tid;
                const unsigned long long* ovr = (const unsigned long long*)ov64w;
                unsigned long long Mlo = ovr[t] & below_mask(t);
                unsigned long long Mhi = ovr[t + 32] & below_mask(t + 32);
                unsigned long long K = ~0ULL;   // all 64 valid, no prior kept
                while (true) {
                    bool badlo = ((K >> t) & 1ULL) && (Mlo & K);
                    bool badhi = ((K >> (t + 32)) & 1ULL) && (Mhi & K);
                    unsigned bl = __ballot_sync(0xffffffffu, badlo);
                    unsigned bh = __ballot_sync(0xffffffffu, badhi);
                    unsigned long long bad = (unsigned long long)bl |
                                             ((unsigned long long)bh << 32);
                    if (!bad) break;
                    K &= ~(bad & (0ULL - bad));
                }
                if (t == 0) { s_k64 = K; s_cnt64 = __popcll(K); }
            }
            __syncthreads();
            if (s_cnt64 >= NUM_PRED) {
                // selection + output entirely within top-64
                unsigned long long k64 = s_k64;
                if (tid < 64) {
                    bool kept = (k64 >> tid) & 1ULL;
                    int keptBefore = __popcll(k64 & below_mask(tid));
                    if (kept && keptBefore < NUM_PRED) sel[keptBefore] = tid;
                }
                __syncthreads();
                if (tid < NUM_PRED) {
                    int i = sel[tid];
                    float* o = out + ((size_t)b * NUM_PRED + tid) * 13;
                    write_row(o, sc64[i], bx64[i],
                              y + ((size_t)b * NBOX + sidx64[i]) * NCH);
                }
                return;   // uniform across block
            }
        } else {
            __syncthreads();   // keep barrier count consistent (m64>128 branch)
        }
    }

    // =================== full 400-wide fallback ===================
    int cut = s_cut;
    if (fast) {
        for (int i = tid; i < cc; i += 1024) {
            unsigned long long k = g_cand0[b][i];
            float s = fkey_inv((unsigned int)(k >> 32));
            if (binf(s) >= cut) {
                int p = atomicAdd(&s_m, 1);
                if (p < SORTW) S.u.p1.cand[p] = k;
            }
        }
    } else {
        const float* base = y + (size_t)b * NBOX * NCH + 1;
        for (int i = tid; i < NBOX; i += 1024) {
            float s = base[(size_t)i * NCH];
            if (binc(s) >= cut) {
                int p = atomicAdd(&s_m, 1);
                if (p < SORTW) S.u.p1.cand[p] = mkkey(s, (unsigned int)i);
            }
        }
    }
    __syncthreads();
    int m = s_m; if (m > SORTW) m = SORTW;
    int n = 512; while (n < m) n <<= 1;

    unsigned long long v = (tid < n) ? S.u.p1.cand[tid] : 0ULL;

    for (int k = 2; k <= n; k <<= 1) {
        for (int j = k >> 1; j > 0; j >>= 1) {
            bool keep_max = (((tid & j) == 0) == ((tid & k) == 0));
            unsigned long long o;
            if (j < 32) {
                o = __shfl_xor_sync(0xffffffffu, v, j);
            } else {
                S.u.p1.cand[tid] = v;
                __syncthreads();
                o = S.u.p1.cand[tid ^ j];
                __syncthreads();
            }
            unsigned long long mx = (v > o) ? v : o;
            unsigned long long mn = (v > o) ? o : v;
            v = keep_max ? mx : mn;
        }
    }

    if (tid < NMS_MAX) {
        float s = fkey_inv((unsigned int)(v >> 32));
        unsigned int idx = ~(unsigned int)(v & 0xffffffffu);
        if (idx >= NBOX) idx = 0;
        dsc[tid] = s;
        dsidx[tid] = (int)idx;
        float4 A = decode_box(y + ((size_t)b * NBOX + idx) * NCH);
        dbx[tid*4+0] = A.x; dbx[tid*4+1] = A.y; dbx[tid*4+2] = A.z; dbx[tid*4+3] = A.w;
    }
    __syncthreads();          // phase-1 buffers dead; switch to phase-2 view

    for (int i = tid; i < NMS_MAX; i += 1024) {
        S.u.p2.bxs4[i] = make_float4(dbx[i*4+0], dbx[i*4+1], dbx[i*4+2], dbx[i*4+3]);
        S.u.p2.scs[i] = dsc[i];
    }
    __syncthreads();

    for (int blk = 0; blk < MASKW; ++blk) {
        int rbase = blk * 64;
        int nrows = NMS_MAX - rbase; if (nrows > 64) nrows = 64;
        int nw16  = (blk + 1) * 4;
        int pairs = nrows * nw16;

        for (int p = tid; p < pairs; p += 1024) {
            int r   = p / nw16;
            int w16 = p - r * nw16;
            int j0  = w16 * 16;
            unsigned int mm = 0;
            if (j0 < NMS_MAX) {
                float4 A = S.u.p2.bxs4[rbase + r];
                float areai = (A.z - A.x) * (A.w - A.y);
#pragma unroll 4
                for (int jj = 0; jj < 16; ++jj) {
                    int j = j0 + jj;
                    if (j < NMS_MAX && iou_gt(A, areai, S.u.p2.bxs4[j]))
                        mm |= (1u << jj);
                }
            }
            S.u.p2.ovb16[r * 28 + w16] = (unsigned short)mm;
        }
        __syncthreads();

        if (tid < 32) {
            int t = tid;
            const unsigned long long* ovr = (const unsigned long long*)S.u.p2.ovb16;
            unsigned long long rlo[MASKW], rhi[MASKW];
            float slo = 0.0f, shi = 0.0f;
            int ilo = rbase + t, ihi = ilo + 32;
#pragma unroll
            for (int w = 0; w < MASKW; ++w) {
                rlo[w] = (t < nrows)      ? ovr[t * 7 + w]        : 0ULL;
                rhi[w] = (t + 32 < nrows) ? ovr[(t + 32) * 7 + w] : 0ULL;
            }
            if (ilo < NMS_MAX) slo = S.u.p2.scs[ilo];
            if (ihi < NMS_MAX) shi = S.u.p2.scs[ihi];
            unsigned long long hlo = 0ULL, hhi = 0ULL;
#pragma unroll
            for (int w = 0; w < MASKW; ++w) {
                hlo |= rlo[w] & keepw[w];
                hhi |= rhi[w] & keepw[w];
            }
            bool oklo = (ilo < NMS_MAX) && (slo > 0.01f) && (hlo == 0ULL);
            bool okhi = (ihi < NMS_MAX) && (shi > 0.01f) && (hhi == 0ULL);
            unsigned blo = __ballot_sync(0xffffffffu, oklo);
            unsigned bhi = __ballot_sync(0xffffffffu, okhi);
            unsigned long long K = (unsigned long long)blo |
                                   ((unsigned long long)bhi << 32);
            unsigned long long Mlo = rlo[blk] & below_mask(t);
            unsigned long long Mhi = rhi[blk] & below_mask(t + 32);
            while (true) {
                bool badlo = ((K >> t) & 1ULL) && (Mlo & K);
                bool badhi = ((K >> (t + 32)) & 1ULL) && (Mhi & K);
                unsigned bl = __ballot_sync(0xffffffffu, badlo);
                unsigned bh = __ballot_sync(0xffffffffu, badhi);
                unsigned long long bad = (unsigned long long)bl |
                                         ((unsigned long long)bh << 32);
                if (!bad) break;
                K &= ~(bad & (0ULL - bad));
            }
            if (t == 0) {
                keepw[blk] = K;
                s_cnt += __popcll(K);
                if (s_cnt >= NUM_PRED) s_stop = 1;
            }
        }
        __syncthreads();
        if (s_stop) break;
    }

    if (tid == 0) {
        pp[0] = 0;
#pragma unroll
        for (int w = 0; w < MASKW; ++w) pp[w + 1] = pp[w] + __popcll(keepw[w]);
    }
    __syncthreads();

    if (tid < NMS_MAX) {
        int w = tid >> 6, bit = tid & 63;
        unsigned long long below = keepw[w] & below_mask(bit);
        int keptBefore = pp[w] + __popcll(below);
        bool kept = (keepw[w] >> bit) & 1ULL;
        int K = pp[MASKW];
        if (kept) {
            if (keptBefore < NUM_PRED) { sel[keptBefore] = tid; selk[keptBefore] = 1; }
        } else {
            int r = K + (tid - keptBefore);
            if (r < NUM_PRED) { sel[r] = tid; selk[r] = 0; }
        }
    }
    __syncthreads();

    if (tid < NUM_PRED) {
        int i = sel[tid];
        float* o = out + ((size_t)b * NUM_PRED + tid) * 13;
        float4 A = S.u.p2.bxs4[i];
        write_row(o, selk[tid] ? S.u.p2.scs[i] : -1.0f, A,
                  y + ((size_t)b * NBOX + dsidx[i]) * NCH);
    }
    (void)did64;
}

// ---------------- launch ---------------------------------------------------
extern "C" void kernel_launch(void* const* d_in, const int* in_sizes, int n_in,
                              void* d_out, int out_size) {
    const float* y = (const float*)d_in[0];
    float* out = (float*)d_out;
    k_extract<<<dim3(HBLK, BATCH), 256>>>(y);
    k_tail<<<BATCH, 1024>>>(y, out);
}